// round 2
// baseline (speedup 1.0000x reference)
#include <cuda_runtime.h>

// LightGCN: out = (x + A@x + A@A@x + A@A@A@x) / 4,  A given as COO (row, col, val).
// Strategy: build CSR by row once per call (histogram + scan + scatter), then
// 3x warp-per-row gather-reduce SpMM (no atomics in hot loops), then fused mean.

#define D      128
#define DV     32        // float4 per feature row
#define MAX_N  100032
#define MAX_E  3200000

struct __align__(8) Edge { int c; float v; };

// Scratch (static device memory -- no allocations anywhere)
__device__ int   g_count[MAX_N];
__device__ int   g_cursor[MAX_N];
__device__ int   g_rowptr[MAX_N + 1];
__device__ Edge  g_edges[MAX_E];
__device__ float g_b1[(size_t)MAX_N * D];
__device__ float g_b2[(size_t)MAX_N * D];
__device__ float g_b3[(size_t)MAX_N * D];

// ---------------------------------------------------------------- preprocessing

__global__ void zero_counts_kernel(int n) {
    int i = blockIdx.x * blockDim.x + threadIdx.x;
    if (i < n) { g_count[i] = 0; g_cursor[i] = 0; }
}

__global__ void hist_kernel(const int* __restrict__ rows, int E) {
    int i = blockIdx.x * blockDim.x + threadIdx.x;
    if (i < E) atomicAdd(&g_count[rows[i]], 1);
}

// Single-block exclusive scan over N row counts -> g_rowptr.
__global__ void scan_kernel(int n, int E) {
    __shared__ int s[1024];
    int tid = threadIdx.x;
    int chunk = (n + 1023) / 1024;
    int beg = tid * chunk;
    int end = min(beg + chunk, n);

    int sum = 0;
    for (int i = beg; i < end; ++i) sum += g_count[i];
    s[tid] = sum;
    __syncthreads();

    // Hillis-Steele inclusive scan over the 1024 partials
    for (int off = 1; off < 1024; off <<= 1) {
        int v = (tid >= off) ? s[tid - off] : 0;
        __syncthreads();
        s[tid] += v;
        __syncthreads();
    }

    int run = (tid == 0) ? 0 : s[tid - 1];   // exclusive prefix of this chunk
    for (int i = beg; i < end; ++i) {
        g_rowptr[i] = run;
        run += g_count[i];
    }
    if (tid == 0) g_rowptr[n] = E;
}

__global__ void scatter_kernel(const int* __restrict__ rows,
                               const int* __restrict__ cols,
                               const float* __restrict__ vals, int E) {
    int i = blockIdx.x * blockDim.x + threadIdx.x;
    if (i < E) {
        int r = rows[i];
        int pos = g_rowptr[r] + atomicAdd(&g_cursor[r], 1);
        Edge e;
        e.c = cols[i];
        e.v = vals[i];
        g_edges[pos] = e;   // one STG.64
    }
}

// ---------------------------------------------------------------- SpMM

// One warp per output row. Each lane owns one float4 (4 of the 128 dims).
// Per edge: 8B broadcast edge load + 512B coalesced gather of src[col].
__global__ void spmm_kernel(const float4* __restrict__ src,
                            float4* __restrict__ dst, int n) {
    int w = (blockIdx.x * blockDim.x + threadIdx.x) >> 5;
    int lane = threadIdx.x & 31;
    if (w >= n) return;

    int beg = g_rowptr[w];
    int end = g_rowptr[w + 1];

    float4 acc = make_float4(0.f, 0.f, 0.f, 0.f);
    for (int i = beg; i < end; ++i) {
        Edge e = g_edges[i];                                  // broadcast
        float4 t = __ldg(src + (size_t)e.c * DV + lane);      // coalesced 512B
        acc.x += e.v * t.x;
        acc.y += e.v * t.y;
        acc.z += e.v * t.z;
        acc.w += e.v * t.w;
    }
    dst[(size_t)w * DV + lane] = acc;
}

// ---------------------------------------------------------------- finalize

__global__ void finalize_kernel(const float4* __restrict__ x,
                                float4* __restrict__ out, int n4) {
    int i = blockIdx.x * blockDim.x + threadIdx.x;
    if (i >= n4) return;
    const float4* b1 = (const float4*)g_b1;
    const float4* b2 = (const float4*)g_b2;
    const float4* b3 = (const float4*)g_b3;
    float4 a = x[i], p = b1[i], q = b2[i], r = b3[i];
    float4 o;
    o.x = 0.25f * (a.x + p.x + q.x + r.x);
    o.y = 0.25f * (a.y + p.y + q.y + r.y);
    o.z = 0.25f * (a.z + p.z + q.z + r.z);
    o.w = 0.25f * (a.w + p.w + q.w + r.w);
    out[i] = o;
}

// ---------------------------------------------------------------- launch

extern "C" void kernel_launch(void* const* d_in, const int* in_sizes, int n_in,
                              void* d_out, int out_size) {
    const float* x  = (const float*)d_in[0];
    const int*   er = (const int*)d_in[1];
    const int*   ec = (const int*)d_in[2];
    const float* ev = (const float*)d_in[3];

    int E = in_sizes[1];
    int N = in_sizes[0] / D;

    void *b1p, *b2p, *b3p;
    cudaGetSymbolAddress(&b1p, g_b1);
    cudaGetSymbolAddress(&b2p, g_b2);
    cudaGetSymbolAddress(&b3p, g_b3);

    const int TPB = 256;

    // CSR build
    zero_counts_kernel<<<(N + TPB - 1) / TPB, TPB>>>(N);
    hist_kernel<<<(E + TPB - 1) / TPB, TPB>>>(er, E);
    scan_kernel<<<1, 1024>>>(N, E);
    scatter_kernel<<<(E + TPB - 1) / TPB, TPB>>>(er, ec, ev, E);

    // 3 propagation layers, warp per row
    int spmm_blocks = (N * 32 + TPB - 1) / TPB;
    spmm_kernel<<<spmm_blocks, TPB>>>((const float4*)x,  (float4*)b1p, N);
    spmm_kernel<<<spmm_blocks, TPB>>>((const float4*)b1p, (float4*)b2p, N);
    spmm_kernel<<<spmm_blocks, TPB>>>((const float4*)b2p, (float4*)b3p, N);

    // mean over {x, b1, b2, b3}
    int n4 = N * DV;
    finalize_kernel<<<(n4 + TPB - 1) / TPB, TPB>>>((const float4*)x,
                                                   (float4*)d_out, n4);
}

// round 3
// speedup vs baseline: 1.2451x; 1.2451x over previous
#include <cuda_runtime.h>
#include <cuda_fp16.h>

// LightGCN: out = (x + A@x + A@A@x + A@A@A@x) / 4, COO -> per-call CSR build,
// then warp-per-row gather SpMM. Intermediates in fp16 to halve LTS traffic
// (the measured bottleneck); layer 3 fused with the final mean.

#define D      128
#define DV     32        // float4 per row
#define MAX_N  100032
#define MAX_E  3200000

struct __align__(8) Edge { int c; float v; };

__device__ int    g_count[MAX_N];
__device__ int    g_cursor[MAX_N];
__device__ int    g_rowptr[MAX_N + 1];
__device__ Edge   g_edges[MAX_E];
__device__ __half g_xh [(size_t)MAX_N * D];
__device__ __half g_b1h[(size_t)MAX_N * D];
__device__ __half g_b2h[(size_t)MAX_N * D];

// ---------------------------------------------------------------- preprocessing

__global__ void hist_kernel(const int* __restrict__ rows, int E) {
    int i = blockIdx.x * blockDim.x + threadIdx.x;
    if (i < E) atomicAdd(&g_count[rows[i]], 1);
}

// Single-block exclusive scan over N row counts -> g_rowptr.
__global__ void scan_kernel(int n, int E) {
    __shared__ int s[1024];
    int tid = threadIdx.x;
    int chunk = (n + 1023) / 1024;
    int beg = tid * chunk;
    int end = min(beg + chunk, n);

    int sum = 0;
    for (int i = beg; i < end; ++i) sum += g_count[i];
    s[tid] = sum;
    __syncthreads();

    for (int off = 1; off < 1024; off <<= 1) {
        int v = (tid >= off) ? s[tid - off] : 0;
        __syncthreads();
        s[tid] += v;
        __syncthreads();
    }

    int run = (tid == 0) ? 0 : s[tid - 1];
    for (int i = beg; i < end; ++i) {
        g_rowptr[i] = run;
        run += g_count[i];
    }
    if (tid == 0) g_rowptr[n] = E;
}

__global__ void scatter_kernel(const int* __restrict__ rows,
                               const int* __restrict__ cols,
                               const float* __restrict__ vals, int E) {
    int i = blockIdx.x * blockDim.x + threadIdx.x;
    if (i < E) {
        int r = rows[i];
        int pos = g_rowptr[r] + atomicAdd(&g_cursor[r], 1);
        Edge e;
        e.c = cols[i];
        e.v = vals[i];
        g_edges[pos] = e;
    }
}

// ---------------------------------------------------------------- fp32 -> fp16

__global__ void convert_kernel(const float4* __restrict__ x,
                               uint2* __restrict__ xh, int n4) {
    int i = blockIdx.x * blockDim.x + threadIdx.x;
    if (i >= n4) return;
    float4 v = x[i];
    uint2 o;
    *reinterpret_cast<__half2*>(&o.x) = __floats2half2_rn(v.x, v.y);
    *reinterpret_cast<__half2*>(&o.y) = __floats2half2_rn(v.z, v.w);
    xh[i] = o;
}

// ---------------------------------------------------------------- SpMM (half)

// One warp per output row; lane owns dims [4*lane, 4*lane+4). Per edge:
// 8B broadcast edge load + 256B coalesced half gather. Unrolled x2 for MLP.
__device__ __forceinline__ void gather_fma(float4& acc, float v, uint2 t) {
    float2 lo = __half22float2(*reinterpret_cast<const __half2*>(&t.x));
    float2 hi = __half22float2(*reinterpret_cast<const __half2*>(&t.y));
    acc.x += v * lo.x;
    acc.y += v * lo.y;
    acc.z += v * hi.x;
    acc.w += v * hi.y;
}

__device__ __forceinline__ float4 spmm_row(const uint2* __restrict__ src,
                                           int w, int lane) {
    int beg = g_rowptr[w];
    int end = g_rowptr[w + 1];
    float4 acc = make_float4(0.f, 0.f, 0.f, 0.f);
    int i = beg;
    for (; i + 2 <= end; i += 2) {
        Edge e0 = g_edges[i];
        Edge e1 = g_edges[i + 1];
        uint2 t0 = __ldg(src + (size_t)e0.c * DV + lane);
        uint2 t1 = __ldg(src + (size_t)e1.c * DV + lane);
        gather_fma(acc, e0.v, t0);
        gather_fma(acc, e1.v, t1);
    }
    if (i < end) {
        Edge e = g_edges[i];
        uint2 t = __ldg(src + (size_t)e.c * DV + lane);
        gather_fma(acc, e.v, t);
    }
    return acc;
}

__global__ void spmm_h_kernel(const uint2* __restrict__ src,
                              uint2* __restrict__ dst, int n) {
    int w = (blockIdx.x * blockDim.x + threadIdx.x) >> 5;
    int lane = threadIdx.x & 31;
    if (w >= n) return;
    float4 acc = spmm_row(src, w, lane);
    uint2 o;
    *reinterpret_cast<__half2*>(&o.x) = __floats2half2_rn(acc.x, acc.y);
    *reinterpret_cast<__half2*>(&o.y) = __floats2half2_rn(acc.z, acc.w);
    dst[(size_t)w * DV + lane] = o;
}

// Layer 3 fused with the mean: out = 0.25 * (x + b1 + b2 + A@b2)
__global__ void spmm_final_kernel(const uint2* __restrict__ b2,
                                  const float4* __restrict__ x,
                                  const uint2* __restrict__ b1,
                                  float4* __restrict__ out, int n) {
    int w = (blockIdx.x * blockDim.x + threadIdx.x) >> 5;
    int lane = threadIdx.x & 31;
    if (w >= n) return;
    float4 acc = spmm_row(b2, w, lane);

    size_t idx = (size_t)w * DV + lane;
    float4 xv = x[idx];
    uint2 u1 = b1[idx];
    uint2 u2 = b2[idx];
    float2 a = __half22float2(*reinterpret_cast<const __half2*>(&u1.x));
    float2 b = __half22float2(*reinterpret_cast<const __half2*>(&u1.y));
    float2 c = __half22float2(*reinterpret_cast<const __half2*>(&u2.x));
    float2 d = __half22float2(*reinterpret_cast<const __half2*>(&u2.y));

    float4 o;
    o.x = 0.25f * (xv.x + a.x + c.x + acc.x);
    o.y = 0.25f * (xv.y + a.y + c.y + acc.y);
    o.z = 0.25f * (xv.z + b.x + d.x + acc.z);
    o.w = 0.25f * (xv.w + b.y + d.y + acc.w);
    out[idx] = o;
}

// ---------------------------------------------------------------- launch

extern "C" void kernel_launch(void* const* d_in, const int* in_sizes, int n_in,
                              void* d_out, int out_size) {
    const float* x  = (const float*)d_in[0];
    const int*   er = (const int*)d_in[1];
    const int*   ec = (const int*)d_in[2];
    const float* ev = (const float*)d_in[3];

    int E = in_sizes[1];
    int N = in_sizes[0] / D;

    void *xhp, *b1p, *b2p, *cntp, *curp;
    cudaGetSymbolAddress(&xhp, g_xh);
    cudaGetSymbolAddress(&b1p, g_b1h);
    cudaGetSymbolAddress(&b2p, g_b2h);
    cudaGetSymbolAddress(&cntp, g_count);
    cudaGetSymbolAddress(&curp, g_cursor);

    const int TPB = 256;
    int n4 = N * DV;

    // CSR build
    cudaMemsetAsync(cntp, 0, (size_t)N * sizeof(int));
    cudaMemsetAsync(curp, 0, (size_t)N * sizeof(int));
    convert_kernel<<<(n4 + TPB - 1) / TPB, TPB>>>((const float4*)x,
                                                  (uint2*)xhp, n4);
    hist_kernel<<<(E + TPB - 1) / TPB, TPB>>>(er, E);
    scan_kernel<<<1, 1024>>>(N, E);
    scatter_kernel<<<(E + TPB - 1) / TPB, TPB>>>(er, ec, ev, E);

    // 3 propagation layers (layer 3 fused with final mean)
    int spmm_blocks = (N * 32 + TPB - 1) / TPB;
    spmm_h_kernel<<<spmm_blocks, TPB>>>((const uint2*)xhp, (uint2*)b1p, N);
    spmm_h_kernel<<<spmm_blocks, TPB>>>((const uint2*)b1p, (uint2*)b2p, N);
    spmm_final_kernel<<<spmm_blocks, TPB>>>((const uint2*)b2p,
                                            (const float4*)x,
                                            (const uint2*)b1p,
                                            (float4*)d_out, N);
}

// round 4
// speedup vs baseline: 1.4996x; 1.2044x over previous
#include <cuda_runtime.h>
#include <cuda_fp16.h>

// LightGCN: out = (x + A@x + A@A@x + A@A@A@x) / 4, COO -> per-call CSR build,
// then warp-per-row gather SpMM (fp16 intermediates), layer 3 fused with mean.
// R4: parallel 3-phase scan, atomic-free scatter (offset captured in hist),
// 4x unrolled SpMM gather loop.

#define D      128
#define DV     32        // float4 per row
#define MAX_N  100032
#define MAX_E  3200000
#define SCAN_B 256       // phase-A block size

struct __align__(8) Edge { int c; float v; };

__device__ int    g_count[MAX_N];
__device__ int    g_offs[MAX_E];          // within-row offset per edge
__device__ int    g_rowptr[MAX_N + 1];
__device__ int    g_blocksum[(MAX_N + SCAN_B - 1) / SCAN_B + 1];
__device__ Edge   g_edges[MAX_E];
__device__ __half g_xh [(size_t)MAX_N * D];
__device__ __half g_b1h[(size_t)MAX_N * D];
__device__ __half g_b2h[(size_t)MAX_N * D];

// ---------------------------------------------------------------- preprocessing

// Histogram; atomicAdd return value doubles as the edge's within-row slot.
__global__ void hist_kernel(const int* __restrict__ rows, int E) {
    int i = blockIdx.x * blockDim.x + threadIdx.x;
    if (i < E) g_offs[i] = atomicAdd(&g_count[rows[i]], 1);
}

// Phase A: per-block reduction of counts (coalesced).
__global__ void scan_reduce_kernel(int n) {
    __shared__ int s[SCAN_B];
    int i = blockIdx.x * SCAN_B + threadIdx.x;
    s[threadIdx.x] = (i < n) ? g_count[i] : 0;
    __syncthreads();
    for (int off = SCAN_B / 2; off > 0; off >>= 1) {
        if (threadIdx.x < off) s[threadIdx.x] += s[threadIdx.x + off];
        __syncthreads();
    }
    if (threadIdx.x == 0) g_blocksum[blockIdx.x] = s[0];
}

// Phase B: single block scans the (<=512) block sums, exclusive.
__global__ void scan_partials_kernel(int nblocks) {
    __shared__ int s[512];
    int tid = threadIdx.x;
    int v = (tid < nblocks) ? g_blocksum[tid] : 0;
    s[tid] = v;
    __syncthreads();
    for (int off = 1; off < 512; off <<= 1) {
        int t = (tid >= off) ? s[tid - off] : 0;
        __syncthreads();
        s[tid] += t;
        __syncthreads();
    }
    if (tid < nblocks) g_blocksum[tid] = s[tid] - v;   // exclusive
}

// Phase C: per-block exclusive scan + block offset -> rowptr.
__global__ void scan_final_kernel(int n, int E) {
    __shared__ int s[SCAN_B];
    int i = blockIdx.x * SCAN_B + threadIdx.x;
    int v = (i < n) ? g_count[i] : 0;
    s[threadIdx.x] = v;
    __syncthreads();
    for (int off = 1; off < SCAN_B; off <<= 1) {
        int t = (threadIdx.x >= off) ? s[threadIdx.x - off] : 0;
        __syncthreads();
        s[threadIdx.x] += t;
        __syncthreads();
    }
    if (i < n) g_rowptr[i] = g_blocksum[blockIdx.x] + s[threadIdx.x] - v;
    if (i == n - 1 || (i == n && threadIdx.x == 0)) g_rowptr[n] = E;
}

// Atomic-free scatter using precomputed offsets.
__global__ void scatter_kernel(const int* __restrict__ rows,
                               const int* __restrict__ cols,
                               const float* __restrict__ vals, int E) {
    int i = blockIdx.x * blockDim.x + threadIdx.x;
    if (i < E) {
        int pos = g_rowptr[rows[i]] + g_offs[i];
        Edge e;
        e.c = cols[i];
        e.v = vals[i];
        g_edges[pos] = e;
    }
}

// ---------------------------------------------------------------- fp32 -> fp16

__global__ void convert_kernel(const float4* __restrict__ x,
                               uint2* __restrict__ xh, int n4) {
    int i = blockIdx.x * blockDim.x + threadIdx.x;
    if (i >= n4) return;
    float4 v = x[i];
    uint2 o;
    *reinterpret_cast<__half2*>(&o.x) = __floats2half2_rn(v.x, v.y);
    *reinterpret_cast<__half2*>(&o.y) = __floats2half2_rn(v.z, v.w);
    xh[i] = o;
}

// ---------------------------------------------------------------- SpMM (half)

__device__ __forceinline__ void gather_fma(float4& acc, float v, uint2 t) {
    float2 lo = __half22float2(*reinterpret_cast<const __half2*>(&t.x));
    float2 hi = __half22float2(*reinterpret_cast<const __half2*>(&t.y));
    acc.x += v * lo.x;
    acc.y += v * lo.y;
    acc.z += v * hi.x;
    acc.w += v * hi.y;
}

// One warp per output row; lane owns dims [4*lane, 4*lane+4).
// 4x unrolled: 4 independent 256B gathers in flight.
__device__ __forceinline__ float4 spmm_row(const uint2* __restrict__ src,
                                           int w, int lane) {
    int beg = g_rowptr[w];
    int end = g_rowptr[w + 1];
    float4 acc = make_float4(0.f, 0.f, 0.f, 0.f);
    int i = beg;
    for (; i + 4 <= end; i += 4) {
        Edge e0 = g_edges[i];
        Edge e1 = g_edges[i + 1];
        Edge e2 = g_edges[i + 2];
        Edge e3 = g_edges[i + 3];
        uint2 t0 = __ldg(src + (size_t)e0.c * DV + lane);
        uint2 t1 = __ldg(src + (size_t)e1.c * DV + lane);
        uint2 t2 = __ldg(src + (size_t)e2.c * DV + lane);
        uint2 t3 = __ldg(src + (size_t)e3.c * DV + lane);
        gather_fma(acc, e0.v, t0);
        gather_fma(acc, e1.v, t1);
        gather_fma(acc, e2.v, t2);
        gather_fma(acc, e3.v, t3);
    }
    for (; i < end; ++i) {
        Edge e = g_edges[i];
        uint2 t = __ldg(src + (size_t)e.c * DV + lane);
        gather_fma(acc, e.v, t);
    }
    return acc;
}

__global__ void spmm_h_kernel(const uint2* __restrict__ src,
                              uint2* __restrict__ dst, int n) {
    int w = (blockIdx.x * blockDim.x + threadIdx.x) >> 5;
    int lane = threadIdx.x & 31;
    if (w >= n) return;
    float4 acc = spmm_row(src, w, lane);
    uint2 o;
    *reinterpret_cast<__half2*>(&o.x) = __floats2half2_rn(acc.x, acc.y);
    *reinterpret_cast<__half2*>(&o.y) = __floats2half2_rn(acc.z, acc.w);
    dst[(size_t)w * DV + lane] = o;
}

// Layer 3 fused with the mean: out = 0.25 * (x + b1 + b2 + A@b2)
__global__ void spmm_final_kernel(const uint2* __restrict__ b2,
                                  const float4* __restrict__ x,
                                  const uint2* __restrict__ b1,
                                  float4* __restrict__ out, int n) {
    int w = (blockIdx.x * blockDim.x + threadIdx.x) >> 5;
    int lane = threadIdx.x & 31;
    if (w >= n) return;
    float4 acc = spmm_row(b2, w, lane);

    size_t idx = (size_t)w * DV + lane;
    float4 xv = x[idx];
    uint2 u1 = b1[idx];
    uint2 u2 = b2[idx];
    float2 a = __half22float2(*reinterpret_cast<const __half2*>(&u1.x));
    float2 b = __half22float2(*reinterpret_cast<const __half2*>(&u1.y));
    float2 c = __half22float2(*reinterpret_cast<const __half2*>(&u2.x));
    float2 d = __half22float2(*reinterpret_cast<const __half2*>(&u2.y));

    float4 o;
    o.x = 0.25f * (xv.x + a.x + c.x + acc.x);
    o.y = 0.25f * (xv.y + a.y + c.y + acc.y);
    o.z = 0.25f * (xv.z + b.x + d.x + acc.z);
    o.w = 0.25f * (xv.w + b.y + d.y + acc.w);
    out[idx] = o;
}

// ---------------------------------------------------------------- launch

extern "C" void kernel_launch(void* const* d_in, const int* in_sizes, int n_in,
                              void* d_out, int out_size) {
    const float* x  = (const float*)d_in[0];
    const int*   er = (const int*)d_in[1];
    const int*   ec = (const int*)d_in[2];
    const float* ev = (const float*)d_in[3];

    int E = in_sizes[1];
    int N = in_sizes[0] / D;

    void *xhp, *b1p, *b2p, *cntp;
    cudaGetSymbolAddress(&xhp, g_xh);
    cudaGetSymbolAddress(&b1p, g_b1h);
    cudaGetSymbolAddress(&b2p, g_b2h);
    cudaGetSymbolAddress(&cntp, g_count);

    const int TPB = 256;
    int n4 = N * DV;
    int nsb = (N + SCAN_B - 1) / SCAN_B;   // scan blocks (<=512 assumed)

    // CSR build
    cudaMemsetAsync(cntp, 0, (size_t)N * sizeof(int));
    convert_kernel<<<(n4 + TPB - 1) / TPB, TPB>>>((const float4*)x,
                                                  (uint2*)xhp, n4);
    hist_kernel<<<(E + TPB - 1) / TPB, TPB>>>(er, E);
    scan_reduce_kernel<<<nsb, SCAN_B>>>(N);
    scan_partials_kernel<<<1, 512>>>(nsb);
    scan_final_kernel<<<nsb, SCAN_B>>>(N, E);
    scatter_kernel<<<(E + TPB - 1) / TPB, TPB>>>(er, ec, ev, E);

    // 3 propagation layers (layer 3 fused with final mean)
    int spmm_blocks = (N * 32 + TPB - 1) / TPB;
    spmm_h_kernel<<<spmm_blocks, TPB>>>((const uint2*)xhp, (uint2*)b1p, N);
    spmm_h_kernel<<<spmm_blocks, TPB>>>((const uint2*)b1p, (uint2*)b2p, N);
    spmm_final_kernel<<<spmm_blocks, TPB>>>((const uint2*)b2p,
                                            (const float4*)x,
                                            (const uint2*)b1p,
                                            (float4*)d_out, N);
}